// round 6
// baseline (speedup 1.0000x reference)
#include <cuda_runtime.h>
#include <cuda_fp16.h>
#include <cstdint>

// Geometry
#define DIN    1024
#define DOUT   1024
#define MTOT   32768            // B*S
#define K2     512              // compacted K (2:4 column-global mask)
#define BM     128
#define BN     128
#define BK     64
#define KCH    (K2 / BK)        // 8
#define MT     (MTOT / BM)      // 256
#define NT     (DOUT / BN)      // 8
#define THREADS 128
#define STAGES 2

// fp16 fragment-major compact operands.
// A tile (mt,kc) = 16KB: frag fi = mtl(8)*4 + ks(4); 512B frag, lane*16B.
// B tile (nt,kc) = 16KB: frag fj = p(8)*4 + ks(4); pair p covers ntiles 2p,2p+1.
#define A_STAGE_BYTES (BM * BK * 2)    // 16384
#define B_STAGE_BYTES (BN * BK * 2)    // 16384
__device__ __align__(128) unsigned char g_xc[(size_t)MT * KCH * A_STAGE_BYTES]; // 32 MB
__device__ __align__(128) unsigned char g_wc[(size_t)NT * KCH * B_STAGE_BYTES]; //  1 MB

// ------------------------------------------------------------------ helpers
__device__ __forceinline__ uint32_t smem_u32(const void* p) {
    uint32_t a;
    asm("{ .reg .u64 t; cvta.to.shared.u64 t, %1; cvt.u32.u64 %0, t; }"
        : "=r"(a) : "l"(p));
    return a;
}
__device__ __forceinline__ uint32_t h2bits(float a, float b) {
    __half2 h = __floats2half2_rn(a, b);
    return *reinterpret_cast<uint32_t*>(&h);
}
__device__ __forceinline__ void cp16(uint32_t dst, const void* src) {
    asm volatile("cp.async.cg.shared.global [%0], [%1], 16;"
                 :: "r"(dst), "l"(src) : "memory");
}
__device__ __forceinline__ void cp_commit() {
    asm volatile("cp.async.commit_group;" ::: "memory");
}
template <int N>
__device__ __forceinline__ void cp_wait() {
    asm volatile("cp.async.wait_group %0;" :: "n"(N) : "memory");
}
__device__ __forceinline__ void lds128(uint32_t (&r)[4], uint32_t addr) {
    asm volatile("ld.shared.v4.u32 {%0,%1,%2,%3}, [%4];"
                 : "=r"(r[0]), "=r"(r[1]), "=r"(r[2]), "=r"(r[3]) : "r"(addr));
}
__device__ __forceinline__ void mma_f16(float (&d)[4], const uint32_t (&a)[4],
                                        uint32_t b0, uint32_t b1) {
    asm volatile(
        "mma.sync.aligned.m16n8k16.row.col.f32.f16.f16.f32 "
        "{%0,%1,%2,%3}, {%4,%5,%6,%7}, {%8,%9}, {%0,%1,%2,%3};"
        : "+f"(d[0]), "+f"(d[1]), "+f"(d[2]), "+f"(d[3])
        : "r"(a[0]), "r"(a[1]), "r"(a[2]), "r"(a[3]), "r"(b0), "r"(b1));
}

// Derive this block's 32 group selectors from mask row 0 (column-global mask).
// Thread t<32 fills s_j0[t], s_j1[t] = lane index (0..3) of the 2 active cols
// of group (kc*32 + t), or -1.
__device__ __forceinline__ void load_group_sel(const float4* __restrict__ mask4,
                                               int kc, int* s_j0, int* s_j1) {
    int t = threadIdx.x;
    if (t < 32) {
        float4 m = mask4[kc * 32 + t];
        float mv[4] = {m.x, m.y, m.z, m.w};
        int j0 = -1, j1 = -1;
        #pragma unroll
        for (int j = 3; j >= 0; j--) {
            if (mv[j] != 0.0f) { j1 = j0; j0 = j; }
        }
        s_j0[t] = j0;
        s_j1[t] = j1;
    }
}

// ------------------------------------------------------------------ prepass
// x compaction, smem-staged: block = (mt, kc) covers 128 rows x 128 orig cols.
__global__ void __launch_bounds__(256) compact_x_kernel(const float4* __restrict__ x4,
                                                        const float4* __restrict__ mask4) {
    __shared__ uint32_t hsw[128 * 34];   // 128 rows x 32 half2-pairs, stride 34
    __shared__ int s_j0[32], s_j1[32];

    const int kc = blockIdx.x & (KCH - 1);
    const int mt = blockIdx.x >> 3;
    const int tid = threadIdx.x;

    load_group_sel(mask4, kc, s_j0, s_j1);
    __syncthreads();

    // phase 1: coalesced float4 reads, select 2-of-4, half2 to smem
    #pragma unroll
    for (int i = 0; i < 16; i++) {
        int idx = tid + 256 * i;
        int row = idx >> 5, gl = idx & 31;
        float4 f = x4[(size_t)(mt * BM + row) * (DIN / 4) + kc * 32 + gl];
        int j0 = s_j0[gl], j1 = s_j1[gl];
        float v0 = (j0 == 0) ? f.x : (j0 == 1) ? f.y : (j0 == 2) ? f.z : f.w;
        float v1 = (j1 == 0) ? f.x : (j1 == 1) ? f.y : (j1 == 2) ? f.z : f.w;
        if (j0 < 0) v0 = 0.0f;
        if (j1 < 0) v1 = 0.0f;
        hsw[row * 34 + gl] = h2bits(v0, v1);
    }
    __syncthreads();

    // phase 2: gather into A-fragment order, coalesced 16B writes
    unsigned char* dst = g_xc + ((size_t)(mt * KCH + kc)) * A_STAGE_BYTES;
    #pragma unroll
    for (int j = 0; j < 4; j++) {
        int o = tid + 256 * j;
        int l = o & 31, fi = o >> 5;
        int ks = fi & 3, mtl = fi >> 2;
        int r = mtl * 16 + (l >> 2);
        int wb = ks * 8 + (l & 3);
        uint4 v;
        v.x = hsw[r * 34 + wb];
        v.y = hsw[(r + 8) * 34 + wb];
        v.z = hsw[r * 34 + wb + 4];
        v.w = hsw[(r + 8) * 34 + wb + 4];
        *reinterpret_cast<uint4*>(dst + o * 16) = v;
    }
}

// w compaction, same smem-staged structure: block = (nt, kc), 128 n x 128 orig k.
__global__ void __launch_bounds__(256) compact_w_kernel(const float4* __restrict__ w4,
                                                        const float4* __restrict__ mask4) {
    __shared__ uint32_t hsw[128 * 34];
    __shared__ int s_j0[32], s_j1[32];

    const int kc = blockIdx.x & (KCH - 1);
    const int nt = blockIdx.x >> 3;
    const int tid = threadIdx.x;

    load_group_sel(mask4, kc, s_j0, s_j1);
    __syncthreads();

    #pragma unroll
    for (int i = 0; i < 16; i++) {
        int idx = tid + 256 * i;
        int row = idx >> 5, gl = idx & 31;        // row = n within tile
        float4 f = w4[(size_t)(nt * BN + row) * (DIN / 4) + kc * 32 + gl];
        int j0 = s_j0[gl], j1 = s_j1[gl];
        float v0 = (j0 == 0) ? f.x : (j0 == 1) ? f.y : (j0 == 2) ? f.z : f.w;
        float v1 = (j1 == 0) ? f.x : (j1 == 1) ? f.y : (j1 == 2) ? f.z : f.w;
        if (j0 < 0) v0 = 0.0f;
        if (j1 < 0) v1 = 0.0f;
        hsw[row * 34 + gl] = h2bits(v0, v1);      // compact cols (2g, 2g+1) @ n=row
    }
    __syncthreads();

    // B-fragment order: fj = p*4+ks; lane 16B = {B[k..k+1][n0]} {B[k+8..][n0]}
    //                                            {B[k..k+1][n0+8]} {B[k+8..][n0+8]}
    unsigned char* dst = g_wc + ((size_t)(nt * KCH + kc)) * B_STAGE_BYTES;
    #pragma unroll
    for (int j = 0; j < 4; j++) {
        int o = tid + 256 * j;
        int l = o & 31, fj = o >> 5;
        int ks = fj & 3, p = fj >> 2;
        int n = p * 16 + (l >> 2);
        int pr = ks * 8 + (l & 3);
        uint4 v;
        v.x = hsw[n * 34 + pr];
        v.y = hsw[n * 34 + pr + 4];
        v.z = hsw[(n + 8) * 34 + pr];
        v.w = hsw[(n + 8) * 34 + pr + 4];
        *reinterpret_cast<uint4*>(dst + o * 16) = v;
    }
}

// ------------------------------------------------------------------ GEMM
// smem: 2 stages x (16KB A + 16KB B) = 64KB -> 3 CTAs/SM.
#define SMEM_BYTES (STAGES * (A_STAGE_BYTES + B_STAGE_BYTES))   // 65536

__global__ void __launch_bounds__(THREADS, 3) gemm_kernel(float* __restrict__ out) {
    extern __shared__ char smem[];
    const uint32_t sA0 = smem_u32(smem);
    const uint32_t sB0 = sA0 + STAGES * A_STAGE_BYTES;

    const int tid = threadIdx.x;
    const int wid = tid >> 5, lid = tid & 31;
    const int nt = blockIdx.x, mt = blockIdx.y;
    const int wm = wid & 1;         // 2 m-warps (64 rows)
    const int wn = wid >> 1;        // 2 n-warps (64 cols = 4 pairs)

    const unsigned char* gA = g_xc + ((size_t)mt * KCH) * A_STAGE_BYTES;
    const unsigned char* gB = g_wc + ((size_t)nt * KCH) * B_STAGE_BYTES;

    auto load_stage = [&](int s, int c) {
        uint32_t dA = sA0 + s * A_STAGE_BYTES + tid * 16;
        const unsigned char* srcA = gA + (size_t)c * A_STAGE_BYTES + tid * 16;
        #pragma unroll
        for (int j = 0; j < 8; j++) cp16(dA + j * 2048, srcA + j * 2048);
        uint32_t dB = sB0 + s * B_STAGE_BYTES + tid * 16;
        const unsigned char* srcB = gB + (size_t)c * B_STAGE_BYTES + tid * 16;
        #pragma unroll
        for (int j = 0; j < 8; j++) cp16(dB + j * 2048, srcB + j * 2048);
    };

    float acc[4][8][4];
    #pragma unroll
    for (int i = 0; i < 4; i++)
        #pragma unroll
        for (int j = 0; j < 8; j++)
            #pragma unroll
            for (int v = 0; v < 4; v++) acc[i][j][v] = 0.0f;

    // prologue: stages 0,1 <- chunks 0,1
    load_stage(0, 0); cp_commit();
    load_stage(1, 1); cp_commit();
    cp_wait<1>();
    __syncthreads();

    for (int c = 0; c < KCH; c++) {
        const int s = c & 1;
        const uint32_t aW = sA0 + s * A_STAGE_BYTES + (wm * 16) * 512 + lid * 16;
        const uint32_t bW = sB0 + s * B_STAGE_BYTES + (wn * 16) * 512 + lid * 16;
        #pragma unroll
        for (int ks = 0; ks < 4; ks++) {
            uint32_t a[4][4], b[4][4];
            #pragma unroll
            for (int i = 0; i < 4; i++) lds128(a[i], aW + (i * 4 + ks) * 512);
            #pragma unroll
            for (int p = 0; p < 4; p++) lds128(b[p], bW + (p * 4 + ks) * 512);
            #pragma unroll
            for (int i = 0; i < 4; i++)
                #pragma unroll
                for (int p = 0; p < 4; p++) {
                    mma_f16(acc[i][2 * p],     a[i], b[p][0], b[p][1]);
                    mma_f16(acc[i][2 * p + 1], a[i], b[p][2], b[p][3]);
                }
        }
        __syncthreads();                    // all warps done reading stage s
        if (c + 2 < KCH) load_stage(s, c + 2);
        cp_commit();
        cp_wait<1>();                       // chunk c+1 landed
        __syncthreads();                    // visible CTA-wide
    }

    // epilogue
    const int rowW = mt * BM + wm * 64 + (lid >> 2);
    const int colW = nt * BN + wn * 64 + (lid & 3) * 2;
    #pragma unroll
    for (int i = 0; i < 4; i++) {
        const size_t r0 = (size_t)(rowW + i * 16) * DOUT;
        const size_t r1 = r0 + (size_t)8 * DOUT;
        #pragma unroll
        for (int j = 0; j < 8; j++) {
            const int cc = colW + j * 8;
            *reinterpret_cast<float2*>(out + r0 + cc) =
                make_float2(acc[i][j][0], acc[i][j][1]);
            *reinterpret_cast<float2*>(out + r1 + cc) =
                make_float2(acc[i][j][2], acc[i][j][3]);
        }
    }
}

// ------------------------------------------------------------------ launch
extern "C" void kernel_launch(void* const* d_in, const int* in_sizes, int n_in,
                              void* d_out, int out_size) {
    const float* x    = (const float*)d_in[0];
    const float* w    = (const float*)d_in[1];
    const float* mask = (const float*)d_in[2];
    float* out        = (float*)d_out;

    cudaFuncSetAttribute(gemm_kernel,
                         cudaFuncAttributeMaxDynamicSharedMemorySize, SMEM_BYTES);

    compact_x_kernel<<<MT * KCH, 256>>>((const float4*)x, (const float4*)mask);
    compact_w_kernel<<<NT * KCH, 256>>>((const float4*)w, (const float4*)mask);
    gemm_kernel<<<dim3(NT, MT), THREADS, SMEM_BYTES>>>(out);
}

// round 7
// speedup vs baseline: 1.2227x; 1.2227x over previous
#include <cuda_runtime.h>
#include <cuda_fp16.h>
#include <cstdint>

// Geometry
#define DIN    1024
#define DOUT   1024
#define MTOT   32768            // B*S
#define K2     512              // compacted K (2:4 column-global mask)
#define BM     128
#define BN     128
#define BK     64
#define KCH    (K2 / BK)        // 8
#define MT     (MTOT / BM)      // 256
#define NT     (DOUT / BN)      // 8
#define THREADS 128
#define STAGES 3

// fp16 fragment-major compact operands.
// A tile (mt,kc) = 16KB: frag fi = mtl(8)*4 + ks(4); 512B frag, lane*16B.
// B tile (nt,kc) = 16KB: frag fj = p(8)*4 + ks(4); pair p covers ntiles 2p,2p+1.
#define A_STAGE_BYTES (BM * BK * 2)    // 16384
#define B_STAGE_BYTES (BN * BK * 2)    // 16384
__device__ __align__(128) unsigned char g_xc[(size_t)MT * KCH * A_STAGE_BYTES]; // 32 MB
__device__ __align__(128) unsigned char g_wc[(size_t)NT * KCH * B_STAGE_BYTES]; //  1 MB

// ------------------------------------------------------------------ helpers
__device__ __forceinline__ uint32_t smem_u32(const void* p) {
    uint32_t a;
    asm("{ .reg .u64 t; cvta.to.shared.u64 t, %1; cvt.u32.u64 %0, t; }"
        : "=r"(a) : "l"(p));
    return a;
}
__device__ __forceinline__ uint32_t h2bits(float a, float b) {
    __half2 h = __floats2half2_rn(a, b);
    return *reinterpret_cast<uint32_t*>(&h);
}
__device__ __forceinline__ void cp16(uint32_t dst, const void* src) {
    asm volatile("cp.async.cg.shared.global [%0], [%1], 16;"
                 :: "r"(dst), "l"(src) : "memory");
}
__device__ __forceinline__ void cp_commit() {
    asm volatile("cp.async.commit_group;" ::: "memory");
}
template <int N>
__device__ __forceinline__ void cp_wait() {
    asm volatile("cp.async.wait_group %0;" :: "n"(N) : "memory");
}
__device__ __forceinline__ void lds128(uint32_t (&r)[4], uint32_t addr) {
    asm volatile("ld.shared.v4.u32 {%0,%1,%2,%3}, [%4];"
                 : "=r"(r[0]), "=r"(r[1]), "=r"(r[2]), "=r"(r[3]) : "r"(addr));
}
__device__ __forceinline__ void mma_f16(float (&d)[4], const uint32_t (&a)[4],
                                        uint32_t b0, uint32_t b1) {
    asm volatile(
        "mma.sync.aligned.m16n8k16.row.col.f32.f16.f16.f32 "
        "{%0,%1,%2,%3}, {%4,%5,%6,%7}, {%8,%9}, {%0,%1,%2,%3};"
        : "+f"(d[0]), "+f"(d[1]), "+f"(d[2]), "+f"(d[3])
        : "r"(a[0]), "r"(a[1]), "r"(a[2]), "r"(a[3]), "r"(b0), "r"(b1));
}

// ------------------------------------------------------------------ prepass
// One kernel: blocks [0, MT*KCH) compact x into A-frag order; blocks
// [MT*KCH, MT*KCH + NT*KCH) compact w into B-frag order. Mask is
// column-global: selectors derived from mask row 0.
__global__ void __launch_bounds__(256) compact_kernel(const float4* __restrict__ x4,
                                                      const float4* __restrict__ w4,
                                                      const float4* __restrict__ mask4) {
    __shared__ uint32_t hsw[128 * 34];   // 128 rows x 32 half2-pairs, stride 34
    __shared__ int s_j0[32], s_j1[32];

    const int b = blockIdx.x;
    const bool isx = (b < MT * KCH);
    const int bb = isx ? b : (b - MT * KCH);
    const int kc = bb & (KCH - 1);
    const int tile = bb >> 3;
    const float4* __restrict__ src = isx ? x4 : w4;
    const int tid = threadIdx.x;

    if (tid < 32) {
        float4 m = mask4[kc * 32 + tid];
        float mv[4] = {m.x, m.y, m.z, m.w};
        int j0 = -1, j1 = -1;
        #pragma unroll
        for (int j = 3; j >= 0; j--)
            if (mv[j] != 0.0f) { j1 = j0; j0 = j; }
        s_j0[tid] = j0;
        s_j1[tid] = j1;
    }
    __syncthreads();

    // phase 1: coalesced float4 reads, batched x8 for MLP; select 2-of-4 -> half2
    #pragma unroll
    for (int h = 0; h < 2; h++) {
        float4 f[8];
        #pragma unroll
        for (int j = 0; j < 8; j++) {
            int idx = tid + 256 * (h * 8 + j);
            int row = idx >> 5, gl = idx & 31;
            f[j] = __ldg(&src[(size_t)(tile * 128 + row) * (DIN / 4) + kc * 32 + gl]);
        }
        #pragma unroll
        for (int j = 0; j < 8; j++) {
            int idx = tid + 256 * (h * 8 + j);
            int row = idx >> 5, gl = idx & 31;
            int j0 = s_j0[gl], j1 = s_j1[gl];
            float v0 = (j0 == 0) ? f[j].x : (j0 == 1) ? f[j].y : (j0 == 2) ? f[j].z : f[j].w;
            float v1 = (j1 == 0) ? f[j].x : (j1 == 1) ? f[j].y : (j1 == 2) ? f[j].z : f[j].w;
            if (j0 < 0) v0 = 0.0f;
            if (j1 < 0) v1 = 0.0f;
            hsw[row * 34 + gl] = h2bits(v0, v1);
        }
    }
    __syncthreads();

    if (isx) {
        // A-fragment order, coalesced 16B writes
        unsigned char* dst = g_xc + ((size_t)(tile * KCH + kc)) * A_STAGE_BYTES;
        #pragma unroll
        for (int j = 0; j < 4; j++) {
            int o = tid + 256 * j;
            int l = o & 31, fi = o >> 5;
            int ks = fi & 3, mtl = fi >> 2;
            int r = mtl * 16 + (l >> 2);
            int wb = ks * 8 + (l & 3);
            uint4 v;
            v.x = hsw[r * 34 + wb];
            v.y = hsw[(r + 8) * 34 + wb];
            v.z = hsw[r * 34 + wb + 4];
            v.w = hsw[(r + 8) * 34 + wb + 4];
            *reinterpret_cast<uint4*>(dst + o * 16) = v;
        }
    } else {
        // B-fragment order: lane 16B = {B[k..k+1][n0]} {B[k+8..k+9][n0]}
        //                              {B[k..k+1][n0+8]} {B[k+8..k+9][n0+8]}
        unsigned char* dst = g_wc + ((size_t)(tile * KCH + kc)) * B_STAGE_BYTES;
        #pragma unroll
        for (int j = 0; j < 4; j++) {
            int o = tid + 256 * j;
            int l = o & 31, fj = o >> 5;
            int ks = fj & 3, p = fj >> 2;
            int n = p * 16 + (l >> 2);
            int pr = ks * 8 + (l & 3);
            uint4 v;
            v.x = hsw[n * 34 + pr];
            v.y = hsw[n * 34 + pr + 4];
            v.z = hsw[(n + 8) * 34 + pr];
            v.w = hsw[(n + 8) * 34 + pr + 4];
            *reinterpret_cast<uint4*>(dst + o * 16) = v;
        }
    }
}

// ------------------------------------------------------------------ GEMM
// R5 configuration: 3 stages x (16KB A + 16KB B) = 96KB, 2 CTAs/SM,
// in-register fragment double buffering, one __syncthreads per chunk.
#define SMEM_BYTES (STAGES * (A_STAGE_BYTES + B_STAGE_BYTES))   // 98304

__global__ void __launch_bounds__(THREADS, 2) gemm_kernel(float* __restrict__ out) {
    extern __shared__ char smem[];
    const uint32_t sA0 = smem_u32(smem);
    const uint32_t sB0 = sA0 + STAGES * A_STAGE_BYTES;

    const int tid = threadIdx.x;
    const int wid = tid >> 5, lid = tid & 31;
    const int nt = blockIdx.x, mt = blockIdx.y;
    const int wm = wid & 1;         // 2 m-warps (64 rows)
    const int wn = wid >> 1;        // 2 n-warps (64 cols = 4 pairs)

    const unsigned char* gA = g_xc + ((size_t)mt * KCH) * A_STAGE_BYTES;
    const unsigned char* gB = g_wc + ((size_t)nt * KCH) * B_STAGE_BYTES;

    auto load_stage = [&](int s, int c) {
        uint32_t dA = sA0 + s * A_STAGE_BYTES + tid * 16;
        const unsigned char* srcA = gA + (size_t)c * A_STAGE_BYTES + tid * 16;
        #pragma unroll
        for (int j = 0; j < 8; j++) cp16(dA + j * 2048, srcA + j * 2048);
        uint32_t dB = sB0 + s * B_STAGE_BYTES + tid * 16;
        const unsigned char* srcB = gB + (size_t)c * B_STAGE_BYTES + tid * 16;
        #pragma unroll
        for (int j = 0; j < 8; j++) cp16(dB + j * 2048, srcB + j * 2048);
    };

    float acc[4][8][4];
    #pragma unroll
    for (int i = 0; i < 4; i++)
        #pragma unroll
        for (int j = 0; j < 8; j++)
            #pragma unroll
            for (int v = 0; v < 4; v++) acc[i][j][v] = 0.0f;

    uint32_t ab[2][4][4], bb[2][4][4];
    auto ldfrags = [&](int buf, int s, int ks) {
        const uint32_t aB = sA0 + s * A_STAGE_BYTES + ((wm * 4) * 4 + ks) * 512 + lid * 16;
        #pragma unroll
        for (int i = 0; i < 4; i++) lds128(ab[buf][i], aB + i * 2048);
        const uint32_t bB = sB0 + s * B_STAGE_BYTES + ((wn * 4) * 4 + ks) * 512 + lid * 16;
        #pragma unroll
        for (int p = 0; p < 4; p++) lds128(bb[buf][p], bB + p * 2048);
    };
    auto domma = [&](int buf) {
        #pragma unroll
        for (int i = 0; i < 4; i++)
            #pragma unroll
            for (int p = 0; p < 4; p++) {
                mma_f16(acc[i][2 * p],     ab[buf][i], bb[buf][p][0], bb[buf][p][1]);
                mma_f16(acc[i][2 * p + 1], ab[buf][i], bb[buf][p][2], bb[buf][p][3]);
            }
    };

    // prologue: fill stages 0,1; load ks0 frags of chunk 0
    load_stage(0, 0); cp_commit();
    load_stage(1, 1); cp_commit();
    cp_wait<1>();
    __syncthreads();
    ldfrags(0, 0, 0);

    int s = 0;
    for (int c = 0; c < KCH; c++) {
        const int snext = (s == STAGES - 1) ? 0 : s + 1;
        const int sload = (snext == STAGES - 1) ? 0 : snext + 1;
        if (c + 2 < KCH) load_stage(sload, c + 2);
        cp_commit();

        ldfrags(1, s, 1); domma(0);     // ks0 compute, ks1 prefetch
        ldfrags(0, s, 2); domma(1);     // ks1
        ldfrags(1, s, 3); domma(0);     // ks2
        cp_wait<1>();                   // chunk c+1 resident (c+2 may pend)
        __syncthreads();                // stage s fully read CTA-wide
        if (c + 1 < KCH) ldfrags(0, snext, 0);
        domma(1);                       // ks3
        s = snext;
    }

    // epilogue: d frag (r,2c): d0,d1 @ row r; d2,d3 @ row r+8
    const int rowW = mt * BM + wm * 64 + (lid >> 2);
    const int colW = nt * BN + wn * 64 + (lid & 3) * 2;
    #pragma unroll
    for (int i = 0; i < 4; i++) {
        const size_t r0 = (size_t)(rowW + i * 16) * DOUT;
        const size_t r1 = r0 + (size_t)8 * DOUT;
        #pragma unroll
        for (int j = 0; j < 8; j++) {
            const int cc = colW + j * 8;
            *reinterpret_cast<float2*>(out + r0 + cc) =
                make_float2(acc[i][j][0], acc[i][j][1]);
            *reinterpret_cast<float2*>(out + r1 + cc) =
                make_float2(acc[i][j][2], acc[i][j][3]);
        }
    }
}

// ------------------------------------------------------------------ launch
extern "C" void kernel_launch(void* const* d_in, const int* in_sizes, int n_in,
                              void* d_out, int out_size) {
    const float* x    = (const float*)d_in[0];
    const float* w    = (const float*)d_in[1];
    const float* mask = (const float*)d_in[2];
    float* out        = (float*)d_out;

    cudaFuncSetAttribute(gemm_kernel,
                         cudaFuncAttributeMaxDynamicSharedMemorySize, SMEM_BYTES);

    compact_kernel<<<MT * KCH + NT * KCH, 256>>>((const float4*)x, (const float4*)w,
                                                 (const float4*)mask);
    gemm_kernel<<<dim3(NT, MT), THREADS, SMEM_BYTES>>>(out);
}

// round 8
// speedup vs baseline: 1.2328x; 1.0083x over previous
#include <cuda_runtime.h>
#include <cuda_fp16.h>
#include <cstdint>

// Geometry
#define DIN    1024
#define DOUT   1024
#define MTOT   32768            // B*S
#define K2     512              // compacted K (2:4 column-global mask)
#define BM     128
#define BN     128
#define BK     64
#define KCH    (K2 / BK)        // 8
#define MT     (MTOT / BM)      // 256
#define NT     (DOUT / BN)      // 8
#define THREADS 128
#define STAGES 3

// fp16 fragment-major compact operands.
// A tile (mt,kc) = 16KB: frag fi = mtl(8)*4 + ks(4); 512B frag, lane*16B.
// B tile (nt,kc) = 16KB: frag fj = p(8)*4 + ks(4); pair p covers ntiles 2p,2p+1.
#define A_STAGE_BYTES (BM * BK * 2)    // 16384
#define B_STAGE_BYTES (BN * BK * 2)    // 16384
__device__ __align__(128) unsigned char g_xc[(size_t)MT * KCH * A_STAGE_BYTES]; // 32 MB
__device__ __align__(128) unsigned char g_wc[(size_t)NT * KCH * B_STAGE_BYTES]; //  1 MB

// smem staging stride (words) for the compact kernel: 36 makes phase-2 gather
// addresses (l>>2)*36 + (l&3) = (l>>2)*4 + (l&3) mod 32 -> all banks distinct.
#define HSTRIDE 36

// ------------------------------------------------------------------ helpers
__device__ __forceinline__ uint32_t smem_u32(const void* p) {
    uint32_t a;
    asm("{ .reg .u64 t; cvta.to.shared.u64 t, %1; cvt.u32.u64 %0, t; }"
        : "=r"(a) : "l"(p));
    return a;
}
__device__ __forceinline__ uint32_t h2bits(float a, float b) {
    __half2 h = __floats2half2_rn(a, b);
    return *reinterpret_cast<uint32_t*>(&h);
}
__device__ __forceinline__ void cp16(uint32_t dst, const void* src) {
    asm volatile("cp.async.cg.shared.global [%0], [%1], 16;"
                 :: "r"(dst), "l"(src) : "memory");
}
__device__ __forceinline__ void cp_commit() {
    asm volatile("cp.async.commit_group;" ::: "memory");
}
template <int N>
__device__ __forceinline__ void cp_wait() {
    asm volatile("cp.async.wait_group %0;" :: "n"(N) : "memory");
}
__device__ __forceinline__ void lds128(uint32_t (&r)[4], uint32_t addr) {
    asm volatile("ld.shared.v4.u32 {%0,%1,%2,%3}, [%4];"
                 : "=r"(r[0]), "=r"(r[1]), "=r"(r[2]), "=r"(r[3]) : "r"(addr));
}
__device__ __forceinline__ void mma_f16(float (&d)[4], const uint32_t (&a)[4],
                                        uint32_t b0, uint32_t b1) {
    asm volatile(
        "mma.sync.aligned.m16n8k16.row.col.f32.f16.f16.f32 "
        "{%0,%1,%2,%3}, {%4,%5,%6,%7}, {%8,%9}, {%0,%1,%2,%3};"
        : "+f"(d[0]), "+f"(d[1]), "+f"(d[2]), "+f"(d[3])
        : "r"(a[0]), "r"(a[1]), "r"(a[2]), "r"(a[3]), "r"(b0), "r"(b1));
}

// ------------------------------------------------------------------ prepass
// One kernel: blocks [0, MT*KCH) compact x into A-frag order; blocks
// [MT*KCH, MT*KCH + NT*KCH) compact w into B-frag order. Mask is
// column-global: selectors derived from mask row 0.
__global__ void __launch_bounds__(256) compact_kernel(const float4* __restrict__ x4,
                                                      const float4* __restrict__ w4,
                                                      const float4* __restrict__ mask4) {
    __shared__ uint32_t hsw[128 * HSTRIDE];   // 128 rows x 32 half2-pairs
    __shared__ int s_j0[32], s_j1[32];

    const int b = blockIdx.x;
    const bool isx = (b < MT * KCH);
    const int bb = isx ? b : (b - MT * KCH);
    const int kc = bb & (KCH - 1);
    const int tile = bb >> 3;
    const float4* __restrict__ src = isx ? x4 : w4;
    const int tid = threadIdx.x;

    if (tid < 32) {
        float4 m = mask4[kc * 32 + tid];
        float mv[4] = {m.x, m.y, m.z, m.w};
        int j0 = -1, j1 = -1;
        #pragma unroll
        for (int j = 3; j >= 0; j--)
            if (mv[j] != 0.0f) { j1 = j0; j0 = j; }
        s_j0[tid] = j0;
        s_j1[tid] = j1;
    }
    __syncthreads();

    // phase 1: coalesced float4 reads, batched x8 for MLP; select 2-of-4 -> half2
    #pragma unroll
    for (int h = 0; h < 2; h++) {
        float4 f[8];
        #pragma unroll
        for (int j = 0; j < 8; j++) {
            int idx = tid + 256 * (h * 8 + j);
            int row = idx >> 5, gl = idx & 31;
            f[j] = __ldg(&src[(size_t)(tile * 128 + row) * (DIN / 4) + kc * 32 + gl]);
        }
        #pragma unroll
        for (int j = 0; j < 8; j++) {
            int idx = tid + 256 * (h * 8 + j);
            int row = idx >> 5, gl = idx & 31;
            int j0 = s_j0[gl], j1 = s_j1[gl];
            float v0 = (j0 == 0) ? f[j].x : (j0 == 1) ? f[j].y : (j0 == 2) ? f[j].z : f[j].w;
            float v1 = (j1 == 0) ? f[j].x : (j1 == 1) ? f[j].y : (j1 == 2) ? f[j].z : f[j].w;
            if (j0 < 0) v0 = 0.0f;
            if (j1 < 0) v1 = 0.0f;
            hsw[row * HSTRIDE + gl] = h2bits(v0, v1);
        }
    }
    __syncthreads();

    if (isx) {
        // A-fragment order, coalesced 16B writes
        unsigned char* dst = g_xc + ((size_t)(tile * KCH + kc)) * A_STAGE_BYTES;
        #pragma unroll
        for (int j = 0; j < 4; j++) {
            int o = tid + 256 * j;
            int l = o & 31, fi = o >> 5;
            int ks = fi & 3, mtl = fi >> 2;
            int r = mtl * 16 + (l >> 2);
            int wb = ks * 8 + (l & 3);
            uint4 v;
            v.x = hsw[r * HSTRIDE + wb];
            v.y = hsw[(r + 8) * HSTRIDE + wb];
            v.z = hsw[r * HSTRIDE + wb + 4];
            v.w = hsw[(r + 8) * HSTRIDE + wb + 4];
            *reinterpret_cast<uint4*>(dst + o * 16) = v;
        }
    } else {
        // B-fragment order: lane 16B = {B[k..k+1][n0]} {B[k+8..k+9][n0]}
        //                              {B[k..k+1][n0+8]} {B[k+8..k+9][n0+8]}
        unsigned char* dst = g_wc + ((size_t)(tile * KCH + kc)) * B_STAGE_BYTES;
        #pragma unroll
        for (int j = 0; j < 4; j++) {
            int o = tid + 256 * j;
            int l = o & 31, fj = o >> 5;
            int ks = fj & 3, p = fj >> 2;
            int n = p * 16 + (l >> 2);
            int pr = ks * 8 + (l & 3);
            uint4 v;
            v.x = hsw[n * HSTRIDE + pr];
            v.y = hsw[n * HSTRIDE + pr + 4];
            v.z = hsw[(n + 8) * HSTRIDE + pr];
            v.w = hsw[(n + 8) * HSTRIDE + pr + 4];
            *reinterpret_cast<uint4*>(dst + o * 16) = v;
        }
    }
}

// ------------------------------------------------------------------ GEMM
// R5/R7 configuration (DO NOT TOUCH): 3 stages x (16KB A + 16KB B) = 96KB,
// 2 CTAs/SM, in-register fragment double buffering, one __syncthreads/chunk.
#define SMEM_BYTES (STAGES * (A_STAGE_BYTES + B_STAGE_BYTES))   // 98304

__global__ void __launch_bounds__(THREADS, 2) gemm_kernel(float* __restrict__ out) {
    extern __shared__ char smem[];
    const uint32_t sA0 = smem_u32(smem);
    const uint32_t sB0 = sA0 + STAGES * A_STAGE_BYTES;

    const int tid = threadIdx.x;
    const int wid = tid >> 5, lid = tid & 31;
    const int nt = blockIdx.x, mt = blockIdx.y;
    const int wm = wid & 1;         // 2 m-warps (64 rows)
    const int wn = wid >> 1;        // 2 n-warps (64 cols = 4 pairs)

    const unsigned char* gA = g_xc + ((size_t)mt * KCH) * A_STAGE_BYTES;
    const unsigned char* gB = g_wc + ((size_t)nt * KCH) * B_STAGE_BYTES;

    auto load_stage = [&](int s, int c) {
        uint32_t dA = sA0 + s * A_STAGE_BYTES + tid * 16;
        const unsigned char* srcA = gA + (size_t)c * A_STAGE_BYTES + tid * 16;
        #pragma unroll
        for (int j = 0; j < 8; j++) cp16(dA + j * 2048, srcA + j * 2048);
        uint32_t dB = sB0 + s * B_STAGE_BYTES + tid * 16;
        const unsigned char* srcB = gB + (size_t)c * B_STAGE_BYTES + tid * 16;
        #pragma unroll
        for (int j = 0; j < 8; j++) cp16(dB + j * 2048, srcB + j * 2048);
    };

    float acc[4][8][4];
    #pragma unroll
    for (int i = 0; i < 4; i++)
        #pragma unroll
        for (int j = 0; j < 8; j++)
            #pragma unroll
            for (int v = 0; v < 4; v++) acc[i][j][v] = 0.0f;

    uint32_t ab[2][4][4], bb[2][4][4];
    auto ldfrags = [&](int buf, int s, int ks) {
        const uint32_t aB = sA0 + s * A_STAGE_BYTES + ((wm * 4) * 4 + ks) * 512 + lid * 16;
        #pragma unroll
        for (int i = 0; i < 4; i++) lds128(ab[buf][i], aB + i * 2048);
        const uint32_t bB = sB0 + s * B_STAGE_BYTES + ((wn * 4) * 4 + ks) * 512 + lid * 16;
        #pragma unroll
        for (int p = 0; p < 4; p++) lds128(bb[buf][p], bB + p * 2048);
    };
    auto domma = [&](int buf) {
        #pragma unroll
        for (int i = 0; i < 4; i++)
            #pragma unroll
            for (int p = 0; p < 4; p++) {
                mma_f16(acc[i][2 * p],     ab[buf][i], bb[buf][p][0], bb[buf][p][1]);
                mma_f16(acc[i][2 * p + 1], ab[buf][i], bb[buf][p][2], bb[buf][p][3]);
            }
    };

    // prologue: fill stages 0,1; load ks0 frags of chunk 0
    load_stage(0, 0); cp_commit();
    load_stage(1, 1); cp_commit();
    cp_wait<1>();
    __syncthreads();
    ldfrags(0, 0, 0);

    int s = 0;
    for (int c = 0; c < KCH; c++) {
        const int snext = (s == STAGES - 1) ? 0 : s + 1;
        const int sload = (snext == STAGES - 1) ? 0 : snext + 1;
        if (c + 2 < KCH) load_stage(sload, c + 2);
        cp_commit();

        ldfrags(1, s, 1); domma(0);     // ks0 compute, ks1 prefetch
        ldfrags(0, s, 2); domma(1);     // ks1
        ldfrags(1, s, 3); domma(0);     // ks2
        cp_wait<1>();                   // chunk c+1 resident (c+2 may pend)
        __syncthreads();                // stage s fully read CTA-wide
        if (c + 1 < KCH) ldfrags(0, snext, 0);
        domma(1);                       // ks3
        s = snext;
    }

    // epilogue: d frag (r,2c): d0,d1 @ row r; d2,d3 @ row r+8
    const int rowW = mt * BM + wm * 64 + (lid >> 2);
    const int colW = nt * BN + wn * 64 + (lid & 3) * 2;
    #pragma unroll
    for (int i = 0; i < 4; i++) {
        const size_t r0 = (size_t)(rowW + i * 16) * DOUT;
        const size_t r1 = r0 + (size_t)8 * DOUT;
        #pragma unroll
        for (int j = 0; j < 8; j++) {
            const int cc = colW + j * 8;
            *reinterpret_cast<float2*>(out + r0 + cc) =
                make_float2(acc[i][j][0], acc[i][j][1]);
            *reinterpret_cast<float2*>(out + r1 + cc) =
                make_float2(acc[i][j][2], acc[i][j][3]);
        }
    }
}

// ------------------------------------------------------------------ launch
extern "C" void kernel_launch(void* const* d_in, const int* in_sizes, int n_in,
                              void* d_out, int out_size) {
    const float* x    = (const float*)d_in[0];
    const float* w    = (const float*)d_in[1];
    const float* mask = (const float*)d_in[2];
    float* out        = (float*)d_out;

    cudaFuncSetAttribute(gemm_kernel,
                         cudaFuncAttributeMaxDynamicSharedMemorySize, SMEM_BYTES);

    compact_kernel<<<MT * KCH + NT * KCH, 256>>>((const float4*)x, (const float4*)w,
                                                 (const float4*)mask);
    gemm_kernel<<<dim3(NT, MT), THREADS, SMEM_BYTES>>>(out);
}